// round 3
// baseline (speedup 1.0000x reference)
#include <cuda_runtime.h>
#include <cstdint>

#define BATCH 16
#define NPTS  9216
#define CH    256
#define KC    21
#define KP    24
#define ITERS 20
#define SUB   64
#define XS    260          // floats per point row; %32==4 => conflict-free LDS.128/STS.128
#define THREADS 128
#define MAXCTA 288
#define SCP   25           // scores row pitch (odd => conflict-free)

// ---------------- persistent device state (no allocations allowed) ----------------
__device__ float g_cent[BATCH*KC*CH];
__device__ float g_csq[BATCH*KC];
__device__ unsigned long long g_part[MAXCTA*KC*(CH/2)];   // f32x2 bins, per-CTA
__device__ int   g_pcnt[MAXCTA*KC];
__device__ unsigned int g_bar_cnt;
__device__ volatile unsigned int g_bar_gen;

__device__ __forceinline__ void fma2(unsigned long long &d, unsigned long long a,
                                     unsigned long long b) {
    asm("fma.rn.f32x2 %0, %1, %2, %0;" : "+l"(d) : "l"(a), "l"(b));
}
__device__ __forceinline__ void add2(unsigned long long &d, unsigned long long a) {
    asm("add.rn.f32x2 %0, %0, %1;" : "+l"(d) : "l"(a));
}
__device__ __forceinline__ float2 u2f2(unsigned long long v) {
    float2 f; asm("mov.b64 {%0, %1}, %2;" : "=f"(f.x), "=f"(f.y) : "l"(v)); return f;
}

// grid-wide barrier: generation counter, replay-safe
__device__ __forceinline__ void gridbar(unsigned nct) {
    __syncthreads();
    if (threadIdx.x == 0) {
        unsigned g = g_bar_gen;
        __threadfence();
        unsigned a = atomicAdd(&g_bar_cnt, 1u);
        if (a == nct - 1u) {
            g_bar_cnt = 0u;
            __threadfence();
            g_bar_gen = g + 1u;
        } else {
            while (g_bar_gen == g) { __nanosleep(64); }
        }
        __threadfence();
    }
    __syncthreads();
}

// async-copy one 64-point subtile into padded smem layout
__device__ __forceinline__ void cp_subtile(const float* __restrict__ xb,
                                           float* x_s, int st, int tid) {
    const float* src = xb + (size_t)st*SUB*CH;
    unsigned sbase = (unsigned)__cvta_generic_to_shared(x_s);
    #pragma unroll
    for (int l = 0; l < (SUB*CH/4)/THREADS; ++l) {   // 32 x 16B per thread
        int idx = l*THREADS + tid;
        int n = idx >> 6, cq = idx & 63;
        unsigned dst = sbase + (unsigned)((n*XS + cq*4)*4);
        const float* s = src + n*CH + cq*4;
        asm volatile("cp.async.cg.shared.global [%0], [%1], 16;" :: "r"(dst), "l"(s));
    }
    asm volatile("cp.async.commit_group;" ::: "memory");
}

// dot partials for one (cq-half, k-range): TN=2 points, TK clusters
template<int TK>
__device__ __forceinline__ void dot_half(const float* x_s, const float* cent,
                                         float* scores, int lane, int h, int k0,
                                         int store_mode) {
    unsigned long long acc[2][TK][2];
    #pragma unroll
    for (int i = 0; i < 2; ++i)
        #pragma unroll
        for (int j = 0; j < TK; ++j) { acc[i][j][0] = 0ull; acc[i][j][1] = 0ull; }

    const int cq0 = h << 5;
    #pragma unroll 2
    for (int c = 0; c < 32; ++c) {
        int cq = cq0 + c;
        ulonglong2 cv[TK];
        #pragma unroll
        for (int j = 0; j < TK; ++j)
            cv[j] = *(const ulonglong2*)(cent + (k0+j)*CH + (cq<<2));
        #pragma unroll
        for (int i = 0; i < 2; ++i) {
            ulonglong2 xq = *(const ulonglong2*)(x_s + (lane + (i<<5))*XS + (cq<<2));
            #pragma unroll
            for (int j = 0; j < TK; ++j) {
                fma2(acc[i][j][0], xq.x, cv[j].x);
                fma2(acc[i][j][1], xq.y, cv[j].y);
            }
        }
    }
    #pragma unroll
    for (int i = 0; i < 2; ++i) {
        int pt = lane + (i<<5);
        #pragma unroll
        for (int j = 0; j < TK; ++j) {
            float2 a0 = u2f2(acc[i][j][0]);
            float2 a1 = u2f2(acc[i][j][1]);
            float dot = (a0.x+a0.y)+(a1.x+a1.y);
            if (store_mode) scores[pt*SCP + k0 + j] = dot;
            else            scores[pt*SCP + k0 + j] += dot;
        }
    }
}

extern "C" __global__ void __launch_bounds__(THREADS, 2)
kmeans_persist(const float* __restrict__ x, const void* __restrict__ ip,
               float* __restrict__ out, int cpb) {
    extern __shared__ float sm[];
    float* x_s    = sm;                     // 16640 f
    float* cent   = x_s + SUB*XS;           // 5376 f
    float* scores = cent + KC*CH;           // 64*25 = 1600 f (also finalize scratch)
    float* csq_s  = scores + SUB*SCP;       // 24 f
    int*   icnt   = (int*)(csq_s + KP);     // 24
    int*   off    = icnt + KP;              // 24
    int*   order  = off + KP;               // 64
    int*   ks     = order + SUB;            // 64
    int*   asg    = ks + SUB;               // 64
    int*   flag   = asg + SUB;              // 8

    const unsigned nct = gridDim.x;
    const int bid = blockIdx.x;
    const int tid = threadIdx.x;
    const int b     = bid / cpb;
    const int chunk = bid % cpb;
    const int ppc   = NPTS / cpb;
    const int nsub  = ppc / SUB;
    const float* xb = x + ((size_t)b*NPTS + (size_t)chunk*ppc)*CH;

    const int lane = tid & 31;
    const int wid  = tid >> 5;
    const int h    = wid >> 1;        // cq-half
    const int kg   = wid & 1;         // k-group: 0 -> k 0..10, 1 -> k 11..20
    unsigned long long* x_u = (unsigned long long*)x_s;
    unsigned long long* gp  = g_part + (size_t)bid*KC*(CH/2);
    const float INF = __int_as_float(0x7f800000);

    // ---- int64 vs int32 init_idx detection ----
    if (tid == 0) {
        const unsigned long long* p = (const unsigned long long*)ip;
        int any = 0;
        #pragma unroll 8
        for (int i = 0; i < (BATCH*KC)/2; ++i) any |= ((p[i] >> 32) != 0ull);
        flag[0] = any ? 0 : 1;   // 1 => int64
    }
    __syncthreads();
    const int is64 = flag[0];

    // ---- init: gather initial centroids + 0.5*||c||^2 ----
    for (int task = bid; task < BATCH*KC; task += nct) {
        int tb = task / KC;
        long long idx = is64 ? ((const long long*)ip)[task]
                             : (long long)((const int*)ip)[task];
        const float* src = x + ((size_t)tb*NPTS + (size_t)idx)*CH;
        float v0 = src[tid], v1 = src[tid+128];
        g_cent[task*CH + tid]       = v0;
        g_cent[task*CH + tid + 128] = v1;
        float sq = v0*v0 + v1*v1;
        #pragma unroll
        for (int o = 16; o > 0; o >>= 1) sq += __shfl_xor_sync(~0u, sq, o);
        if ((tid & 31) == 0) scores[tid >> 5] = sq;
        __syncthreads();
        if (tid == 0) g_csq[task] = 0.5f*(scores[0]+scores[1]+scores[2]+scores[3]);
        __syncthreads();
    }
    gridbar(nct);

    // ---------------- main iteration loop ----------------
    for (int it = 0; it < ITERS; ++it) {
        cp_subtile(xb, x_s, 0, tid);     // prefetch subtile 0 under cent load
        for (int t = tid; t < KC*CH/4; t += THREADS)
            ((float4*)cent)[t] = ((const float4*)(g_cent + (size_t)b*KC*CH))[t];
        if (tid < KP) csq_s[tid] = (tid < KC) ? g_csq[b*KC + tid] : INF;
        if (tid < KP) icnt[tid] = 0;
        // zero own g_part slots (thread-exclusive, no sync needed before own RMWs)
        #pragma unroll
        for (int k = 0; k < KC; ++k) gp[k*(CH/2) + tid] = 0ull;
        __syncthreads();

        for (int st = 0; st < nsub; ++st) {
            asm volatile("cp.async.wait_group 0;" ::: "memory");
            __syncthreads();

            // ---- dots: 2 cq-halves x 2 k-groups, partials into scores ----
            if (h == 0) {
                if (kg == 0) dot_half<11>(x_s, cent, scores, lane, 0, 0, 1);
                else         dot_half<10>(x_s, cent, scores, lane, 0, 11, 1);
            }
            __syncthreads();
            if (h == 1) {
                if (kg == 0) dot_half<11>(x_s, cent, scores, lane, 1, 0, 0);
                else         dot_half<10>(x_s, cent, scores, lane, 1, 11, 0);
            }
            __syncthreads();

            // ---- argmin (ascending k, strict <) ----
            if (tid < SUB) {
                float bs = INF; int bk = 0;
                #pragma unroll
                for (int k = 0; k < KC; ++k) {
                    float s = csq_s[k] - scores[tid*SCP + k];  // 0.5||c||^2 - x.c
                    if (s < bs) { bs = s; bk = k; }
                }
                asg[tid] = bk;
                atomicAdd(&icnt[bk], 1);
            }
            __syncthreads();

            // ---- deterministic counting sort by cluster ----
            if (tid == 0) {
                int acc = 0;
                #pragma unroll
                for (int k = 0; k < KC; ++k) { off[k] = acc; acc += 0; }
                // compute offsets from per-subtile histogram
            }
            // build per-subtile histogram offsets via scan of asg (warp 0)
            if (tid < KC) {
                int c = 0;
                #pragma unroll 8
                for (int i = 0; i < SUB; ++i) c += (asg[i] == tid);
                off[tid] = c;
            }
            __syncthreads();
            if (tid == 0) {
                int acc = 0;
                #pragma unroll
                for (int k = 0; k < KC; ++k) { int c = off[k]; off[k] = acc; acc += c; }
            }
            __syncthreads();
            if (tid < KC) {
                int pos = off[tid];
                #pragma unroll 8
                for (int i = 0; i < SUB; ++i)
                    if (asg[i] == tid) { order[pos] = i; ks[pos] = tid; ++pos; }
            }
            __syncthreads();

            // ---- run accumulation: register acc per run, flush to global bins ----
            {
                unsigned long long acc = 0ull;
                int cur = ks[0];
                #pragma unroll 4
                for (int j = 0; j < SUB; ++j) {
                    int i = order[j];
                    int k = ks[j];
                    if (k != cur) {
                        unsigned long long t = gp[cur*(CH/2) + tid];
                        add2(t, acc);
                        gp[cur*(CH/2) + tid] = t;
                        acc = 0ull; cur = k;
                    }
                    add2(acc, x_u[i*(XS/2) + tid]);
                }
                unsigned long long t = gp[cur*(CH/2) + tid];
                add2(t, acc);
                gp[cur*(CH/2) + tid] = t;
            }
            __syncthreads();

            if (st + 1 < nsub) cp_subtile(xb, x_s, st+1, tid);
        }

        if (tid < KC) g_pcnt[bid*KC + tid] = icnt[tid];
        gridbar(nct);

        // ---- finalize: fixed-order reduction over chunks ----
        for (int task = bid; task < BATCH*KC; task += nct) {
            int tb = task / KC, tk = task % KC;
            float s0 = 0.f, s1 = 0.f; int cnt = 0;
            for (int c = 0; c < cpb; ++c) {
                const float* pp = (const float*)(g_part + ((size_t)(tb*cpb + c)*KC + tk)*(CH/2));
                s0 += pp[tid]; s1 += pp[tid+128];
                cnt += g_pcnt[(tb*cpb + c)*KC + tk];
            }
            float v0, v1;
            if (cnt > 0) { v0 = s0 / (float)cnt; v1 = s1 / (float)cnt; }
            else { v0 = g_cent[task*CH+tid]; v1 = g_cent[task*CH+tid+128]; }
            g_cent[task*CH+tid]     = v0;
            g_cent[task*CH+tid+128] = v1;
            if (it == ITERS-1) { out[task*CH+tid] = v0; out[task*CH+tid+128] = v1; }
            float sq = v0*v0 + v1*v1;
            #pragma unroll
            for (int o = 16; o > 0; o >>= 1) sq += __shfl_xor_sync(~0u, sq, o);
            if ((tid & 31) == 0) scores[tid >> 5] = sq;
            __syncthreads();
            if (tid == 0) g_csq[task] = 0.5f*(scores[0]+scores[1]+scores[2]+scores[3]);
            __syncthreads();
        }
        gridbar(nct);
    }
}

extern "C" void kernel_launch(void* const* d_in, const int* in_sizes, int n_in,
                              void* d_out, int out_size) {
    const float* x  = (const float*)d_in[0];
    const void*  ip = d_in[1];
    float* out = (float*)d_out;

    const int smem_bytes = (SUB*XS + KC*CH + SUB*SCP + KP)*4
                         + (KP + KP + SUB + SUB + SUB + 8)*4;   // ~96.5 KB
    cudaFuncSetAttribute(kmeans_persist, cudaFuncAttributeMaxDynamicSharedMemorySize, smem_bytes);

    int occ = 0;
    cudaOccupancyMaxActiveBlocksPerMultiprocessor(&occ, kmeans_persist, THREADS, smem_bytes);
    int sms = 0;
    cudaDeviceGetAttribute(&sms, cudaDevAttrMultiProcessorCount, 0);

    int cpb, grid;
    if (occ >= 2 && sms*2 >= 288) { cpb = 18; grid = 288; }   // 2 CTAs/SM
    else                          { cpb = 9;  grid = 144; }   // fallback, 1 CTA/SM

    kmeans_persist<<<grid, THREADS, smem_bytes>>>(x, ip, out, cpb);
}